// round 1
// baseline (speedup 1.0000x reference)
#include <cuda_runtime.h>
#include <cstdint>

#define Bb 4
#define Ss 1024
#define Ee 1024
#define Hh 16
#define Dd 64
#define BH (Bb*Hh)      // 64
#define Mm (Bb*Ss)      // 4096

// ---------------- scratch (static device globals; no allocation) ----------------
__device__ float g_Q[BH * Ss * Dd];          // 16 MB  [bh][s][d]
__device__ float g_K[BH * Ss * Dd];          // 16 MB
__device__ float g_Sc[(size_t)BH * Ss * Ss]; // 256 MB [bh][q][k]
__device__ float g_m[BH * Ss];               // col max
__device__ float g_rZ[BH * Ss];              // 1 / col sumexp
__device__ float g_AO[Mm * Ee];              // 16 MB  [b*S+q][h*D+d]

// ---------------- f32x2 packed-FMA helpers (Blackwell FFMA2) ----------------
__device__ __forceinline__ void fma2(unsigned long long& d,
                                     unsigned long long a,
                                     unsigned long long b) {
    asm("fma.rn.f32x2 %0, %1, %2, %0;" : "+l"(d) : "l"(a), "l"(b));
}
__device__ __forceinline__ unsigned long long pack_dup(float x) {
    unsigned long long r;
    asm("mov.b64 %0, {%1, %1};" : "=l"(r) : "f"(x));
    return r;
}
__device__ __forceinline__ float2 unpack2(unsigned long long v) {
    float2 r;
    asm("mov.b64 {%0, %1}, %2;" : "=f"(r.x), "=f"(r.y) : "l"(v));
    return r;
}

// ============================================================================
// Kernel 1: Q = x @ Wq[h] + bq[h],  K = x @ Wk[h] + bk[h]
// grid (Mm/64, H), block 256. Tile 64(m) x 64(d=full head), k-chunk 16.
// ============================================================================
__global__ __launch_bounds__(256) void k_proj(
    const float* __restrict__ x,
    const float* __restrict__ Wq, const float* __restrict__ bq,
    const float* __restrict__ Wk, const float* __restrict__ bk)
{
    __shared__ __align__(16) float As[16][64];
    __shared__ __align__(16) float Bq[16][64];
    __shared__ __align__(16) float Bk[16][64];

    const int h  = blockIdx.y;
    const int m0 = blockIdx.x << 6;
    const int t  = threadIdx.x;
    const int tx = t & 15, ty = t >> 4;

    const int ar = t >> 2, ac = (t & 3) << 2;   // A-tile: row 0..63, col4 base
    const int br = t >> 4, bc = (t & 15) << 2;  // B-tile: k-row 0..15, col base

    const float* __restrict__ wqh = Wq + h * (Ee * Dd);
    const float* __restrict__ wkh = Wk + h * (Ee * Dd);

    unsigned long long aq[4][2], ak[4][2];
#pragma unroll
    for (int i = 0; i < 4; i++) { aq[i][0]=0ULL; aq[i][1]=0ULL; ak[i][0]=0ULL; ak[i][1]=0ULL; }

    for (int e0 = 0; e0 < Ee; e0 += 16) {
        float4 av  = *(const float4*)(x   + (m0 + ar) * Ee + e0 + ac);
        float4 bqv = *(const float4*)(wqh + (e0 + br) * Dd + bc);
        float4 bkv = *(const float4*)(wkh + (e0 + br) * Dd + bc);
        __syncthreads();
        As[ac + 0][ar] = av.x; As[ac + 1][ar] = av.y;
        As[ac + 2][ar] = av.z; As[ac + 3][ar] = av.w;
        *(float4*)&Bq[br][bc] = bqv;
        *(float4*)&Bk[br][bc] = bkv;
        __syncthreads();
#pragma unroll
        for (int kk = 0; kk < 16; kk++) {
            float4 a = *(const float4*)&As[kk][ty << 2];
            ulonglong2 b0 = *(const ulonglong2*)&Bq[kk][tx << 2];
            ulonglong2 b1 = *(const ulonglong2*)&Bk[kk][tx << 2];
            unsigned long long a0 = pack_dup(a.x), a1 = pack_dup(a.y),
                               a2 = pack_dup(a.z), a3 = pack_dup(a.w);
            fma2(aq[0][0], a0, b0.x); fma2(aq[0][1], a0, b0.y);
            fma2(ak[0][0], a0, b1.x); fma2(ak[0][1], a0, b1.y);
            fma2(aq[1][0], a1, b0.x); fma2(aq[1][1], a1, b0.y);
            fma2(ak[1][0], a1, b1.x); fma2(ak[1][1], a1, b1.y);
            fma2(aq[2][0], a2, b0.x); fma2(aq[2][1], a2, b0.y);
            fma2(ak[2][0], a2, b1.x); fma2(ak[2][1], a2, b1.y);
            fma2(aq[3][0], a3, b0.x); fma2(aq[3][1], a3, b0.y);
            fma2(ak[3][0], a3, b1.x); fma2(ak[3][1], a3, b1.y);
        }
    }

    const int b    = m0 >> 10;         // m0 / S
    const int s0   = m0 & (Ss - 1);
    const int base = (b * Hh + h) * Ss;
    const int d0   = tx << 2;
    float4 biasq = *(const float4*)(bq + h * Dd + d0);
    float4 biask = *(const float4*)(bk + h * Dd + d0);
#pragma unroll
    for (int i = 0; i < 4; i++) {
        int s = s0 + (ty << 2) + i;
        float2 lo, hi;
        lo = unpack2(aq[i][0]); hi = unpack2(aq[i][1]);
        *(float4*)(g_Q + (base + s) * Dd + d0) =
            make_float4(lo.x + biasq.x, lo.y + biasq.y, hi.x + biasq.z, hi.y + biasq.w);
        lo = unpack2(ak[i][0]); hi = unpack2(ak[i][1]);
        *(float4*)(g_K + (base + s) * Dd + d0) =
            make_float4(lo.x + biask.x, lo.y + biask.y, hi.x + biask.z, hi.y + biask.w);
    }
}

// ============================================================================
// Kernel 2: Sc[bh][q][k] = (1/32) * sum_d Q[q,d] * K[k,d]
// grid (S/64 k-tiles, S/64 q-tiles, BH), block 256. Full D=64 in smem.
// ============================================================================
__global__ __launch_bounds__(256) void k_scores()
{
    __shared__ __align__(16) float Qs[64][64];  // [d][q]
    __shared__ __align__(16) float Ks[64][64];  // [d][k]

    const int bh = blockIdx.z;
    const int q0 = blockIdx.y << 6;
    const int k0 = blockIdx.x << 6;
    const int t  = threadIdx.x;
    const int tx = t & 15, ty = t >> 4;
    const int r  = t & 63;

    const float* Qg = g_Q + (bh * Ss + q0 + r) * Dd;
    const float* Kg = g_K + (bh * Ss + k0 + r) * Dd;
#pragma unroll
    for (int rep = 0; rep < 4; rep++) {
        int c = (((t >> 6) + (rep << 2)) << 2);      // 0..60 step 4
        float4 qv = *(const float4*)(Qg + c);
        float4 kv = *(const float4*)(Kg + c);
        Qs[c + 0][r] = qv.x; Qs[c + 1][r] = qv.y; Qs[c + 2][r] = qv.z; Qs[c + 3][r] = qv.w;
        Ks[c + 0][r] = kv.x; Ks[c + 1][r] = kv.y; Ks[c + 2][r] = kv.z; Ks[c + 3][r] = kv.w;
    }
    __syncthreads();

    unsigned long long acc[4][2];
#pragma unroll
    for (int i = 0; i < 4; i++) { acc[i][0] = 0ULL; acc[i][1] = 0ULL; }

#pragma unroll 16
    for (int d = 0; d < 64; d++) {
        float4 a = *(const float4*)&Qs[d][ty << 2];
        ulonglong2 bb = *(const ulonglong2*)&Ks[d][tx << 2];
        unsigned long long a0 = pack_dup(a.x), a1 = pack_dup(a.y),
                           a2 = pack_dup(a.z), a3 = pack_dup(a.w);
        fma2(acc[0][0], a0, bb.x); fma2(acc[0][1], a0, bb.y);
        fma2(acc[1][0], a1, bb.x); fma2(acc[1][1], a1, bb.y);
        fma2(acc[2][0], a2, bb.x); fma2(acc[2][1], a2, bb.y);
        fma2(acc[3][0], a3, bb.x); fma2(acc[3][1], a3, bb.y);
    }

    const float sc = 1.0f / 32.0f;  // 1/sqrt(S)
    float* outp = g_Sc + (size_t)bh * Ss * Ss;
#pragma unroll
    for (int i = 0; i < 4; i++) {
        float2 lo = unpack2(acc[i][0]), hi = unpack2(acc[i][1]);
        *(float4*)(outp + (q0 + (ty << 2) + i) * Ss + k0 + (tx << 2)) =
            make_float4(lo.x * sc, lo.y * sc, hi.x * sc, hi.y * sc);
    }
}

// ============================================================================
// Kernel 3: per-column (over q) online max & sum-exp.  grid (S/256, BH).
// ============================================================================
__global__ __launch_bounds__(256) void k_colstats()
{
    const int bh = blockIdx.y;
    const int k  = (blockIdx.x << 8) + threadIdx.x;
    const float* p = g_Sc + (size_t)bh * Ss * Ss + k;
    float mx = -1e30f, z = 0.0f;
#pragma unroll 8
    for (int q = 0; q < Ss; q++) {
        float s  = p[(size_t)q * Ss];
        float nm = fmaxf(mx, s);
        z = z * __expf(mx - nm) + __expf(s - nm);
        mx = nm;
    }
    g_m[bh * Ss + k]  = mx;
    g_rZ[bh * Ss + k] = 1.0f / z;
}

// ============================================================================
// Kernel 4: out[q,d] = sum_k exp(Sc[q,k]-m[k]) * rZ[k] * Q[k,d]   (v == q bug)
// grid (S/64 q-tiles, BH), block 256. Tile 64(q) x 64(d), k-chunk 16.
// Writes g_AO in [b*S+q][h*D+d] layout (head-concat done here).
// ============================================================================
__global__ __launch_bounds__(256) void k_av()
{
    __shared__ __align__(16) float Ps[16][64];  // [kk][q]
    __shared__ __align__(16) float Vs[16][64];  // [kk][d]

    const int bh = blockIdx.y;
    const int q0 = blockIdx.x << 6;
    const int t  = threadIdx.x;
    const int tx = t & 15, ty = t >> 4;
    const int pr = t >> 2, pc = (t & 3) << 2;   // P: q-row 0..63, k col4 base
    const int vr = t >> 4, vc = (t & 15) << 2;  // V: k-row 0..15, d col base

    const float* mrow = g_m  + bh * Ss;
    const float* zrow = g_rZ + bh * Ss;
    const float* Scb  = g_Sc + (size_t)bh * Ss * Ss + (size_t)(q0 + pr) * Ss;

    unsigned long long acc[4][2];
#pragma unroll
    for (int i = 0; i < 4; i++) { acc[i][0] = 0ULL; acc[i][1] = 0ULL; }

    for (int k0 = 0; k0 < Ss; k0 += 16) {
        float4 sv = *(const float4*)(Scb + k0 + pc);
        float4 mv = *(const float4*)(mrow + k0 + pc);
        float4 zv = *(const float4*)(zrow + k0 + pc);
        float4 vv = *(const float4*)(g_Q + (bh * Ss + k0 + vr) * Dd + vc);
        __syncthreads();
        Ps[pc + 0][pr] = __expf(sv.x - mv.x) * zv.x;
        Ps[pc + 1][pr] = __expf(sv.y - mv.y) * zv.y;
        Ps[pc + 2][pr] = __expf(sv.z - mv.z) * zv.z;
        Ps[pc + 3][pr] = __expf(sv.w - mv.w) * zv.w;
        *(float4*)&Vs[vr][vc] = vv;
        __syncthreads();
#pragma unroll
        for (int kk = 0; kk < 16; kk++) {
            float4 a = *(const float4*)&Ps[kk][ty << 2];
            ulonglong2 bb = *(const ulonglong2*)&Vs[kk][tx << 2];
            unsigned long long a0 = pack_dup(a.x), a1 = pack_dup(a.y),
                               a2 = pack_dup(a.z), a3 = pack_dup(a.w);
            fma2(acc[0][0], a0, bb.x); fma2(acc[0][1], a0, bb.y);
            fma2(acc[1][0], a1, bb.x); fma2(acc[1][1], a1, bb.y);
            fma2(acc[2][0], a2, bb.x); fma2(acc[2][1], a2, bb.y);
            fma2(acc[3][0], a3, bb.x); fma2(acc[3][1], a3, bb.y);
        }
    }

    const int b = bh >> 4, h = bh & 15;
    const int d0 = (tx << 2);
#pragma unroll
    for (int i = 0; i < 4; i++) {
        int q = q0 + (ty << 2) + i;
        float2 lo = unpack2(acc[i][0]), hi = unpack2(acc[i][1]);
        *(float4*)(g_AO + (b * Ss + q) * Ee + h * Dd + d0) =
            make_float4(lo.x, lo.y, hi.x, hi.y);
    }
}

// ============================================================================
// Kernel 5: out = AO @ Wo + bo.  grid (Mm/64, Ee/64), block 256.
// ============================================================================
__global__ __launch_bounds__(256) void k_oproj(
    const float* __restrict__ Wo, const float* __restrict__ bo,
    float* __restrict__ out)
{
    __shared__ __align__(16) float As[16][64];
    __shared__ __align__(16) float Bs[16][64];

    const int m0 = blockIdx.x << 6;
    const int n0 = blockIdx.y << 6;
    const int t  = threadIdx.x;
    const int tx = t & 15, ty = t >> 4;
    const int ar = t >> 2, ac = (t & 3) << 2;
    const int br = t >> 4, bc = (t & 15) << 2;

    unsigned long long acc[4][2];
#pragma unroll
    for (int i = 0; i < 4; i++) { acc[i][0] = 0ULL; acc[i][1] = 0ULL; }

    for (int e0 = 0; e0 < Ee; e0 += 16) {
        float4 av = *(const float4*)(g_AO + (m0 + ar) * Ee + e0 + ac);
        float4 bv = *(const float4*)(Wo + (e0 + br) * Ee + n0 + bc);
        __syncthreads();
        As[ac + 0][ar] = av.x; As[ac + 1][ar] = av.y;
        As[ac + 2][ar] = av.z; As[ac + 3][ar] = av.w;
        *(float4*)&Bs[br][bc] = bv;
        __syncthreads();
#pragma unroll
        for (int kk = 0; kk < 16; kk++) {
            float4 a = *(const float4*)&As[kk][ty << 2];
            ulonglong2 bb = *(const ulonglong2*)&Bs[kk][tx << 2];
            unsigned long long a0 = pack_dup(a.x), a1 = pack_dup(a.y),
                               a2 = pack_dup(a.z), a3 = pack_dup(a.w);
            fma2(acc[0][0], a0, bb.x); fma2(acc[0][1], a0, bb.y);
            fma2(acc[1][0], a1, bb.x); fma2(acc[1][1], a1, bb.y);
            fma2(acc[2][0], a2, bb.x); fma2(acc[2][1], a2, bb.y);
            fma2(acc[3][0], a3, bb.x); fma2(acc[3][1], a3, bb.y);
        }
    }

    float4 bias = *(const float4*)(bo + n0 + (tx << 2));
#pragma unroll
    for (int i = 0; i < 4; i++) {
        float2 lo = unpack2(acc[i][0]), hi = unpack2(acc[i][1]);
        *(float4*)(out + (m0 + (ty << 2) + i) * Ee + n0 + (tx << 2)) =
            make_float4(lo.x + bias.x, lo.y + bias.y, hi.x + bias.z, hi.y + bias.w);
    }
}

// ============================================================================
extern "C" void kernel_launch(void* const* d_in, const int* in_sizes, int n_in,
                              void* d_out, int out_size)
{
    const float* x  = (const float*)d_in[0];
    const float* Wq = (const float*)d_in[1];
    const float* bq = (const float*)d_in[2];
    const float* Wk = (const float*)d_in[3];
    const float* bk = (const float*)d_in[4];
    // d_in[5] = W_v, d_in[6] = b_v: intentionally unused (reference bug v = q)
    const float* Wo = (const float*)d_in[7];
    const float* bo = (const float*)d_in[8];
    float* out = (float*)d_out;

    k_proj   <<<dim3(Mm / 64, Hh), 256>>>(x, Wq, bq, Wk, bk);
    k_scores <<<dim3(Ss / 64, Ss / 64, BH), 256>>>();
    k_colstats<<<dim3(Ss / 256, BH), 256>>>();
    k_av     <<<dim3(Ss / 64, BH), 256>>>();
    k_oproj  <<<dim3(Mm / 64, Ee / 64), 256>>>(Wo, bo, out);
}

// round 2
// speedup vs baseline: 1.0009x; 1.0009x over previous
#include <cuda_runtime.h>
#include <cstdint>

#define Bb 4
#define Ss 1024
#define Ee 1024
#define Hh 16
#define Dd 64
#define BH (Bb*Hh)      // 64
#define Mm (Bb*Ss)      // 4096

// ---------------- scratch (static device globals; no allocation) ----------------
__device__ float g_Q[BH * Ss * Dd];          // 16 MB  [bh][s][d]
__device__ float g_K[BH * Ss * Dd];          // 16 MB
__device__ float g_Sc[(size_t)BH * Ss * Ss]; // 256 MB [bh][q][k]
__device__ float g_m[BH * Ss];               // col max
__device__ float g_rZ[BH * Ss];              // 1 / col sumexp
__device__ float g_AO[Mm * Ee];              // 16 MB  [b*S+q][h*D+d]

// ---------------- f32x2 packed-FMA helpers (Blackwell FFMA2) ----------------
__device__ __forceinline__ void fma2(unsigned long long& d,
                                     unsigned long long a,
                                     unsigned long long b) {
    asm("fma.rn.f32x2 %0, %1, %2, %0;" : "+l"(d) : "l"(a), "l"(b));
}
__device__ __forceinline__ unsigned long long pack_dup(float x) {
    unsigned long long r;
    asm("mov.b64 %0, {%1, %1};" : "=l"(r) : "f"(x));
    return r;
}
__device__ __forceinline__ float2 unpack2(unsigned long long v) {
    float2 r;
    asm("mov.b64 {%0, %1}, %2;" : "=f"(r.x), "=f"(r.y) : "l"(v));
    return r;
}

// ============================================================================
// Kernel 1: Q = x @ Wq[h] + bq[h],  K = x @ Wk[h] + bk[h]
// grid (Mm/64, H), block 256. Tile 64(m) x 64(d=full head), k-chunk 16.
// ============================================================================
__global__ __launch_bounds__(256) void k_proj(
    const float* __restrict__ x,
    const float* __restrict__ Wq, const float* __restrict__ bq,
    const float* __restrict__ Wk, const float* __restrict__ bk)
{
    __shared__ __align__(16) float As[16][64];
    __shared__ __align__(16) float Bq[16][64];
    __shared__ __align__(16) float Bk[16][64];

    const int h  = blockIdx.y;
    const int m0 = blockIdx.x << 6;
    const int t  = threadIdx.x;
    const int tx = t & 15, ty = t >> 4;

    const int ar = t >> 2, ac = (t & 3) << 2;   // A-tile: row 0..63, col4 base
    const int br = t >> 4, bc = (t & 15) << 2;  // B-tile: k-row 0..15, col base

    const float* __restrict__ wqh = Wq + h * (Ee * Dd);
    const float* __restrict__ wkh = Wk + h * (Ee * Dd);

    unsigned long long aq[4][2], ak[4][2];
#pragma unroll
    for (int i = 0; i < 4; i++) { aq[i][0]=0ULL; aq[i][1]=0ULL; ak[i][0]=0ULL; ak[i][1]=0ULL; }

    for (int e0 = 0; e0 < Ee; e0 += 16) {
        float4 av  = *(const float4*)(x   + (m0 + ar) * Ee + e0 + ac);
        float4 bqv = *(const float4*)(wqh + (e0 + br) * Dd + bc);
        float4 bkv = *(const float4*)(wkh + (e0 + br) * Dd + bc);
        __syncthreads();
        As[ac + 0][ar] = av.x; As[ac + 1][ar] = av.y;
        As[ac + 2][ar] = av.z; As[ac + 3][ar] = av.w;
        *(float4*)&Bq[br][bc] = bqv;
        *(float4*)&Bk[br][bc] = bkv;
        __syncthreads();
#pragma unroll
        for (int kk = 0; kk < 16; kk++) {
            float4 a = *(const float4*)&As[kk][ty << 2];
            ulonglong2 b0 = *(const ulonglong2*)&Bq[kk][tx << 2];
            ulonglong2 b1 = *(const ulonglong2*)&Bk[kk][tx << 2];
            unsigned long long a0 = pack_dup(a.x), a1 = pack_dup(a.y),
                               a2 = pack_dup(a.z), a3 = pack_dup(a.w);
            fma2(aq[0][0], a0, b0.x); fma2(aq[0][1], a0, b0.y);
            fma2(ak[0][0], a0, b1.x); fma2(ak[0][1], a0, b1.y);
            fma2(aq[1][0], a1, b0.x); fma2(aq[1][1], a1, b0.y);
            fma2(ak[1][0], a1, b1.x); fma2(ak[1][1], a1, b1.y);
            fma2(aq[2][0], a2, b0.x); fma2(aq[2][1], a2, b0.y);
            fma2(ak[2][0], a2, b1.x); fma2(ak[2][1], a2, b1.y);
            fma2(aq[3][0], a3, b0.x); fma2(aq[3][1], a3, b0.y);
            fma2(ak[3][0], a3, b1.x); fma2(ak[3][1], a3, b1.y);
        }
    }

    const int b    = m0 >> 10;         // m0 / S
    const int s0   = m0 & (Ss - 1);
    const int base = (b * Hh + h) * Ss;
    const int d0   = tx << 2;
    float4 biasq = *(const float4*)(bq + h * Dd + d0);
    float4 biask = *(const float4*)(bk + h * Dd + d0);
#pragma unroll
    for (int i = 0; i < 4; i++) {
        int s = s0 + (ty << 2) + i;
        float2 lo, hi;
        lo = unpack2(aq[i][0]); hi = unpack2(aq[i][1]);
        *(float4*)(g_Q + (base + s) * Dd + d0) =
            make_float4(lo.x + biasq.x, lo.y + biasq.y, hi.x + biasq.z, hi.y + biasq.w);
        lo = unpack2(ak[i][0]); hi = unpack2(ak[i][1]);
        *(float4*)(g_K + (base + s) * Dd + d0) =
            make_float4(lo.x + biask.x, lo.y + biask.y, hi.x + biask.z, hi.y + biask.w);
    }
}

// ============================================================================
// Kernel 2: Sc[bh][q][k] = (1/32) * sum_d Q[q,d] * K[k,d]
// grid (S/64 k-tiles, S/64 q-tiles, BH), block 256. Full D=64 in smem.
// ============================================================================
__global__ __launch_bounds__(256) void k_scores()
{
    __shared__ __align__(16) float Qs[64][64];  // [d][q]
    __shared__ __align__(16) float Ks[64][64];  // [d][k]

    const int bh = blockIdx.z;
    const int q0 = blockIdx.y << 6;
    const int k0 = blockIdx.x << 6;
    const int t  = threadIdx.x;
    const int tx = t & 15, ty = t >> 4;
    const int r  = t & 63;

    const float* Qg = g_Q + (bh * Ss + q0 + r) * Dd;
    const float* Kg = g_K + (bh * Ss + k0 + r) * Dd;
#pragma unroll
    for (int rep = 0; rep < 4; rep++) {
        int c = (((t >> 6) + (rep << 2)) << 2);      // 0..60 step 4
        float4 qv = *(const float4*)(Qg + c);
        float4 kv = *(const float4*)(Kg + c);
        Qs[c + 0][r] = qv.x; Qs[c + 1][r] = qv.y; Qs[c + 2][r] = qv.z; Qs[c + 3][r] = qv.w;
        Ks[c + 0][r] = kv.x; Ks[c + 1][r] = kv.y; Ks[c + 2][r] = kv.z; Ks[c + 3][r] = kv.w;
    }
    __syncthreads();

    unsigned long long acc[4][2];
#pragma unroll
    for (int i = 0; i < 4; i++) { acc[i][0] = 0ULL; acc[i][1] = 0ULL; }

#pragma unroll 16
    for (int d = 0; d < 64; d++) {
        float4 a = *(const float4*)&Qs[d][ty << 2];
        ulonglong2 bb = *(const ulonglong2*)&Ks[d][tx << 2];
        unsigned long long a0 = pack_dup(a.x), a1 = pack_dup(a.y),
                           a2 = pack_dup(a.z), a3 = pack_dup(a.w);
        fma2(acc[0][0], a0, bb.x); fma2(acc[0][1], a0, bb.y);
        fma2(acc[1][0], a1, bb.x); fma2(acc[1][1], a1, bb.y);
        fma2(acc[2][0], a2, bb.x); fma2(acc[2][1], a2, bb.y);
        fma2(acc[3][0], a3, bb.x); fma2(acc[3][1], a3, bb.y);
    }

    const float sc = 1.0f / 32.0f;  // 1/sqrt(S)
    float* outp = g_Sc + (size_t)bh * Ss * Ss;
#pragma unroll
    for (int i = 0; i < 4; i++) {
        float2 lo = unpack2(acc[i][0]), hi = unpack2(acc[i][1]);
        *(float4*)(outp + (q0 + (ty << 2) + i) * Ss + k0 + (tx << 2)) =
            make_float4(lo.x * sc, lo.y * sc, hi.x * sc, hi.y * sc);
    }
}

// ============================================================================
// Kernel 3: per-column (over q) online max & sum-exp.  grid (S/256, BH).
// ============================================================================
__global__ __launch_bounds__(256) void k_colstats()
{
    const int bh = blockIdx.y;
    const int k  = (blockIdx.x << 8) + threadIdx.x;
    const float* p = g_Sc + (size_t)bh * Ss * Ss + k;
    float mx = -1e30f, z = 0.0f;
#pragma unroll 8
    for (int q = 0; q < Ss; q++) {
        float s  = p[(size_t)q * Ss];
        float nm = fmaxf(mx, s);
        z = z * __expf(mx - nm) + __expf(s - nm);
        mx = nm;
    }
    g_m[bh * Ss + k]  = mx;
    g_rZ[bh * Ss + k] = 1.0f / z;
}

// ============================================================================
// Kernel 4: out[q,d] = sum_k exp(Sc[q,k]-m[k]) * rZ[k] * Q[k,d]   (v == q bug)
// grid (S/64 q-tiles, BH), block 256. Tile 64(q) x 64(d), k-chunk 16.
// Writes g_AO in [b*S+q][h*D+d] layout (head-concat done here).
// ============================================================================
__global__ __launch_bounds__(256) void k_av()
{
    __shared__ __align__(16) float Ps[16][64];  // [kk][q]
    __shared__ __align__(16) float Vs[16][64];  // [kk][d]

    const int bh = blockIdx.y;
    const int q0 = blockIdx.x << 6;
    const int t  = threadIdx.x;
    const int tx = t & 15, ty = t >> 4;
    const int pr = t >> 2, pc = (t & 3) << 2;   // P: q-row 0..63, k col4 base
    const int vr = t >> 4, vc = (t & 15) << 2;  // V: k-row 0..15, d col base

    const float* mrow = g_m  + bh * Ss;
    const float* zrow = g_rZ + bh * Ss;
    const float* Scb  = g_Sc + (size_t)bh * Ss * Ss + (size_t)(q0 + pr) * Ss;

    unsigned long long acc[4][2];
#pragma unroll
    for (int i = 0; i < 4; i++) { acc[i][0] = 0ULL; acc[i][1] = 0ULL; }

    for (int k0 = 0; k0 < Ss; k0 += 16) {
        float4 sv = *(const float4*)(Scb + k0 + pc);
        float4 mv = *(const float4*)(mrow + k0 + pc);
        float4 zv = *(const float4*)(zrow + k0 + pc);
        float4 vv = *(const float4*)(g_Q + (bh * Ss + k0 + vr) * Dd + vc);
        __syncthreads();
        Ps[pc + 0][pr] = __expf(sv.x - mv.x) * zv.x;
        Ps[pc + 1][pr] = __expf(sv.y - mv.y) * zv.y;
        Ps[pc + 2][pr] = __expf(sv.z - mv.z) * zv.z;
        Ps[pc + 3][pr] = __expf(sv.w - mv.w) * zv.w;
        *(float4*)&Vs[vr][vc] = vv;
        __syncthreads();
#pragma unroll
        for (int kk = 0; kk < 16; kk++) {
            float4 a = *(const float4*)&Ps[kk][ty << 2];
            ulonglong2 bb = *(const ulonglong2*)&Vs[kk][tx << 2];
            unsigned long long a0 = pack_dup(a.x), a1 = pack_dup(a.y),
                               a2 = pack_dup(a.z), a3 = pack_dup(a.w);
            fma2(acc[0][0], a0, bb.x); fma2(acc[0][1], a0, bb.y);
            fma2(acc[1][0], a1, bb.x); fma2(acc[1][1], a1, bb.y);
            fma2(acc[2][0], a2, bb.x); fma2(acc[2][1], a2, bb.y);
            fma2(acc[3][0], a3, bb.x); fma2(acc[3][1], a3, bb.y);
        }
    }

    const int b = bh >> 4, h = bh & 15;
    const int d0 = (tx << 2);
#pragma unroll
    for (int i = 0; i < 4; i++) {
        int q = q0 + (ty << 2) + i;
        float2 lo = unpack2(acc[i][0]), hi = unpack2(acc[i][1]);
        *(float4*)(g_AO + (b * Ss + q) * Ee + h * Dd + d0) =
            make_float4(lo.x, lo.y, hi.x, hi.y);
    }
}

// ============================================================================
// Kernel 5: out = AO @ Wo + bo.  grid (Mm/64, Ee/64), block 256.
// ============================================================================
__global__ __launch_bounds__(256) void k_oproj(
    const float* __restrict__ Wo, const float* __restrict__ bo,
    float* __restrict__ out)
{
    __shared__ __align__(16) float As[16][64];
    __shared__ __align__(16) float Bs[16][64];

    const int m0 = blockIdx.x << 6;
    const int n0 = blockIdx.y << 6;
    const int t  = threadIdx.x;
    const int tx = t & 15, ty = t >> 4;
    const int ar = t >> 2, ac = (t & 3) << 2;
    const int br = t >> 4, bc = (t & 15) << 2;

    unsigned long long acc[4][2];
#pragma unroll
    for (int i = 0; i < 4; i++) { acc[i][0] = 0ULL; acc[i][1] = 0ULL; }

    for (int e0 = 0; e0 < Ee; e0 += 16) {
        float4 av = *(const float4*)(g_AO + (m0 + ar) * Ee + e0 + ac);
        float4 bv = *(const float4*)(Wo + (e0 + br) * Ee + n0 + bc);
        __syncthreads();
        As[ac + 0][ar] = av.x; As[ac + 1][ar] = av.y;
        As[ac + 2][ar] = av.z; As[ac + 3][ar] = av.w;
        *(float4*)&Bs[br][bc] = bv;
        __syncthreads();
#pragma unroll
        for (int kk = 0; kk < 16; kk++) {
            float4 a = *(const float4*)&As[kk][ty << 2];
            ulonglong2 bb = *(const ulonglong2*)&Bs[kk][tx << 2];
            unsigned long long a0 = pack_dup(a.x), a1 = pack_dup(a.y),
                               a2 = pack_dup(a.z), a3 = pack_dup(a.w);
            fma2(acc[0][0], a0, bb.x); fma2(acc[0][1], a0, bb.y);
            fma2(acc[1][0], a1, bb.x); fma2(acc[1][1], a1, bb.y);
            fma2(acc[2][0], a2, bb.x); fma2(acc[2][1], a2, bb.y);
            fma2(acc[3][0], a3, bb.x); fma2(acc[3][1], a3, bb.y);
        }
    }

    float4 bias = *(const float4*)(bo + n0 + (tx << 2));
#pragma unroll
    for (int i = 0; i < 4; i++) {
        float2 lo = unpack2(acc[i][0]), hi = unpack2(acc[i][1]);
        *(float4*)(out + (m0 + (ty << 2) + i) * Ee + n0 + (tx << 2)) =
            make_float4(lo.x + bias.x, lo.y + bias.y, hi.x + bias.z, hi.y + bias.w);
    }
}

// ============================================================================
extern "C" void kernel_launch(void* const* d_in, const int* in_sizes, int n_in,
                              void* d_out, int out_size)
{
    const float* x  = (const float*)d_in[0];
    const float* Wq = (const float*)d_in[1];
    const float* bq = (const float*)d_in[2];
    const float* Wk = (const float*)d_in[3];
    const float* bk = (const float*)d_in[4];
    // d_in[5] = W_v, d_in[6] = b_v: intentionally unused (reference bug v = q)
    const float* Wo = (const float*)d_in[7];
    const float* bo = (const float*)d_in[8];
    float* out = (float*)d_out;

    k_proj   <<<dim3(Mm / 64, Hh), 256>>>(x, Wq, bq, Wk, bk);
    k_scores <<<dim3(Ss / 64, Ss / 64, BH), 256>>>();
    k_colstats<<<dim3(Ss / 256, BH), 256>>>();
    k_av     <<<dim3(Ss / 64, BH), 256>>>();
    k_oproj  <<<dim3(Mm / 64, Ee / 64), 256>>>(Wo, bo, out);
}

// round 4
// speedup vs baseline: 1.3088x; 1.3076x over previous
#include <cuda_runtime.h>
#include <cuda_bf16.h>
#include <cstdint>

#define Ss 1024
#define Ee 1024
#define Hh 16
#define Dd 64
#define Bb 4
#define BH 64
#define Mm 4096
#define SA 36   // smem row stride in bf16 (k-chunk 32 + pad 4)

// ----------------- scratch -----------------
__device__ float g_Q [BH * Ss * Dd];
__device__ float g_K [BH * Ss * Dd];
__device__ float g_VT[BH * Dd * Ss];
__device__ float g_Sc[(size_t)BH * Ss * Ss];
__device__ float g_m [BH * Ss];
__device__ float g_rZ[BH * Ss];
__device__ float g_AO[Mm * Ee];
__device__ float g_WqT[Hh * Dd * Ee];
__device__ float g_WkT[Hh * Dd * Ee];
__device__ float g_WoT[Ee * Ee];

// ----------------- helpers -----------------
__device__ __forceinline__ uint32_t pk2(float a, float b) {
    __nv_bfloat16 x = __float2bfloat16(a), y = __float2bfloat16(b);
    uint16_t u = *(uint16_t*)&x, v = *(uint16_t*)&y;
    return (uint32_t)u | ((uint32_t)v << 16);
}
// split-store one float4 into hi/lo bf16 smem rows (4 bf16 each)
__device__ __forceinline__ void splitst(__nv_bfloat16* hp, __nv_bfloat16* lp, float4 v) {
    __nv_bfloat16 hx = __float2bfloat16(v.x), hy = __float2bfloat16(v.y);
    __nv_bfloat16 hz = __float2bfloat16(v.z), hw = __float2bfloat16(v.w);
    *(uint32_t*)hp       = *(uint32_t*)&hx | ((uint32_t)*(uint16_t*)&hy << 16);
    *(uint32_t*)(hp + 2) = *(uint32_t*)&hz | ((uint32_t)*(uint16_t*)&hw << 16);
    *(uint32_t*)lp       = pk2(v.x - __bfloat162float(hx), v.y - __bfloat162float(hy));
    *(uint32_t*)(lp + 2) = pk2(v.z - __bfloat162float(hz), v.w - __bfloat162float(hw));
}
__device__ __forceinline__ void mma16816(float* c, const uint32_t a[4], uint32_t b0, uint32_t b1) {
    asm volatile("mma.sync.aligned.m16n8k16.row.col.f32.bf16.bf16.f32 "
                 "{%0,%1,%2,%3}, {%4,%5,%6,%7}, {%8,%9}, {%0,%1,%2,%3};"
                 : "+f"(c[0]), "+f"(c[1]), "+f"(c[2]), "+f"(c[3])
                 : "r"(a[0]), "r"(a[1]), "r"(a[2]), "r"(a[3]), "r"(b0), "r"(b1));
}

// 3-term split-bf16 compute over one staged k-chunk of 32
template<int NT>
__device__ __forceinline__ void mma_block(
    const __nv_bfloat16* Ah, const __nv_bfloat16* Al,
    const __nv_bfloat16* Bh, const __nv_bfloat16* Bl,
    int wm, int wn, int lane, float acc[4][NT][4])
{
    const int gr = lane >> 2, tc = (lane & 3) * 2;
#pragma unroll
    for (int ks = 0; ks < 32; ks += 16) {
        uint32_t ah[4][4], al[4][4];
#pragma unroll
        for (int mt = 0; mt < 4; mt++) {
            const __nv_bfloat16* pa = Ah + (wm + mt * 16 + gr) * SA + ks + tc;
            const __nv_bfloat16* pl = Al + (wm + mt * 16 + gr) * SA + ks + tc;
            ah[mt][0] = *(const uint32_t*)pa;
            ah[mt][1] = *(const uint32_t*)(pa + 8 * SA);
            ah[mt][2] = *(const uint32_t*)(pa + 8);
            ah[mt][3] = *(const uint32_t*)(pa + 8 * SA + 8);
            al[mt][0] = *(const uint32_t*)pl;
            al[mt][1] = *(const uint32_t*)(pl + 8 * SA);
            al[mt][2] = *(const uint32_t*)(pl + 8);
            al[mt][3] = *(const uint32_t*)(pl + 8 * SA + 8);
        }
#pragma unroll
        for (int nt = 0; nt < NT; nt++) {
            const __nv_bfloat16* pb = Bh + (wn + nt * 8 + gr) * SA + ks + tc;
            const __nv_bfloat16* pq = Bl + (wn + nt * 8 + gr) * SA + ks + tc;
            uint32_t bh0 = *(const uint32_t*)pb, bh1 = *(const uint32_t*)(pb + 8);
            uint32_t bl0 = *(const uint32_t*)pq, bl1 = *(const uint32_t*)(pq + 8);
#pragma unroll
            for (int mt = 0; mt < 4; mt++) {
                mma16816(acc[mt][nt], ah[mt], bh0, bh1);
                mma16816(acc[mt][nt], ah[mt], bl0, bl1);
                mma16816(acc[mt][nt], al[mt], bh0, bh1);
            }
        }
    }
}

// ----------------- transpose: out[z][c][r] = in[z][r][c] -----------------
__global__ void k_tr(const float* __restrict__ in, float* __restrict__ out, int R, int C)
{
    __shared__ float t[32][33];
    const float* I = in  + (size_t)blockIdx.z * R * C;
    float*       O = out + (size_t)blockIdx.z * R * C;
    int r0 = blockIdx.x << 5, c0 = blockIdx.y << 5;
#pragma unroll
    for (int i = threadIdx.y; i < 32; i += 8)
        t[i][threadIdx.x] = I[(size_t)(r0 + i) * C + c0 + threadIdx.x];
    __syncthreads();
#pragma unroll
    for (int i = threadIdx.y; i < 32; i += 8)
        O[(size_t)(c0 + i) * R + r0 + threadIdx.x] = t[threadIdx.x][i];
}

// ============================================================================
// k_proj: [Q|K](128m x 128n) = x @ [WqT;WkT]^T + bias.  grid (32, 16)
// ============================================================================
__global__ __launch_bounds__(256) void k_proj(
    const float* __restrict__ x, const float* __restrict__ bq, const float* __restrict__ bk)
{
    __shared__ __nv_bfloat16 Ah[128 * SA], Al[128 * SA], Bh2[128 * SA], Bl2[128 * SA];
    const int t = threadIdx.x, lane = t & 31, wid = t >> 5;
    const int wm = (wid >> 2) * 64, wn = (wid & 3) * 32;
    const int m0 = blockIdx.x << 7, h = blockIdx.y;
    const float* Wq = g_WqT + (size_t)h * Dd * Ee;
    const float* Wk = g_WkT + (size_t)h * Dd * Ee;

    float acc[4][4][4];
#pragma unroll
    for (int i = 0; i < 4; i++)
#pragma unroll
        for (int j = 0; j < 4; j++)
#pragma unroll
            for (int v = 0; v < 4; v++) acc[i][j][v] = 0.f;

    for (int e0 = 0; e0 < Ee; e0 += 32) {
#pragma unroll
        for (int p = 0; p < 4; p++) {
            int idx = p * 256 + t, row = idx >> 3, k4 = (idx & 7) << 2;
            splitst(&Ah[row * SA + k4], &Al[row * SA + k4],
                    *(const float4*)(x + (size_t)(m0 + row) * Ee + e0 + k4));
            const float* src = (row < 64) ? (Wq + (size_t)row * Ee) : (Wk + (size_t)(row - 64) * Ee);
            splitst(&Bh2[row * SA + k4], &Bl2[row * SA + k4], *(const float4*)(src + e0 + k4));
        }
        __syncthreads();
        mma_block<4>(Ah, Al, Bh2, Bl2, wm, wn, lane, acc);
        __syncthreads();
    }

    const int b = m0 >> 10, hb = b * Hh + h;
    const bool isQ = (wn < 64);
    float* dst = isQ ? g_Q : g_K;
    const float* bias = (isQ ? bq : bk) + h * Dd;
    const int gr = lane >> 2, tc = (lane & 3) * 2;
#pragma unroll
    for (int mt = 0; mt < 4; mt++)
#pragma unroll
        for (int nt = 0; nt < 4; nt++) {
            int d = (wn + nt * 8 + tc) - (isQ ? 0 : 64);
            float bx = bias[d], by = bias[d + 1];
            int s = (m0 & 1023) + wm + mt * 16 + gr;
            *(float2*)(dst + ((size_t)hb * Ss + s) * Dd + d) =
                make_float2(acc[mt][nt][0] + bx, acc[mt][nt][1] + by);
            *(float2*)(dst + ((size_t)hb * Ss + s + 8) * Dd + d) =
                make_float2(acc[mt][nt][2] + bx, acc[mt][nt][3] + by);
        }
}

// ============================================================================
// k_scores: Sc(128q x 128k') = Q @ K^T / 32.  grid (8, 8, 64)
// ============================================================================
__global__ __launch_bounds__(256) void k_scores()
{
    __shared__ __nv_bfloat16 Ah[128 * SA], Al[128 * SA], Bh2[128 * SA], Bl2[128 * SA];
    const int t = threadIdx.x, lane = t & 31, wid = t >> 5;
    const int wm = (wid >> 2) * 64, wn = (wid & 3) * 32;
    const int k0 = blockIdx.x << 7, q0 = blockIdx.y << 7, bh = blockIdx.z;

    float acc[4][4][4];
#pragma unroll
    for (int i = 0; i < 4; i++)
#pragma unroll
        for (int j = 0; j < 4; j++)
#pragma unroll
            for (int v = 0; v < 4; v++) acc[i][j][v] = 0.f;

    for (int e0 = 0; e0 < Dd; e0 += 32) {
#pragma unroll
        for (int p = 0; p < 4; p++) {
            int idx = p * 256 + t, row = idx >> 3, k4 = (idx & 7) << 2;
            splitst(&Ah[row * SA + k4], &Al[row * SA + k4],
                    *(const float4*)(g_Q + ((size_t)bh * Ss + q0 + row) * Dd + e0 + k4));
            splitst(&Bh2[row * SA + k4], &Bl2[row * SA + k4],
                    *(const float4*)(g_K + ((size_t)bh * Ss + k0 + row) * Dd + e0 + k4));
        }
        __syncthreads();
        mma_block<4>(Ah, Al, Bh2, Bl2, wm, wn, lane, acc);
        __syncthreads();
    }

    float* outp = g_Sc + ((size_t)bh << 20);
    const int gr = lane >> 2, tc = (lane & 3) * 2;
#pragma unroll
    for (int mt = 0; mt < 4; mt++)
#pragma unroll
        for (int nt = 0; nt < 4; nt++) {
            int q = q0 + wm + mt * 16 + gr, n = k0 + wn + nt * 8 + tc;
            *(float2*)(outp + (size_t)q * Ss + n) =
                make_float2(acc[mt][nt][0] * 0.03125f, acc[mt][nt][1] * 0.03125f);
            *(float2*)(outp + (size_t)(q + 8) * Ss + n) =
                make_float2(acc[mt][nt][2] * 0.03125f, acc[mt][nt][3] * 0.03125f);
        }
}

// ============================================================================
// k_colstats: per-column (over q) online max & sum-exp.  grid (4, 64)
// ============================================================================
__global__ __launch_bounds__(256) void k_colstats()
{
    const int bh = blockIdx.y;
    const int k  = (blockIdx.x << 8) + threadIdx.x;
    const float* p = g_Sc + ((size_t)bh << 20) + k;
    float mx = -1e30f, z = 0.0f;
#pragma unroll 8
    for (int q = 0; q < Ss; q++) {
        float s  = p[(size_t)q * Ss];
        float nm = fmaxf(mx, s);
        z = z * __expf(mx - nm) + __expf(s - nm);
        mx = nm;
    }
    g_m [bh * Ss + k] = mx;
    g_rZ[bh * Ss + k] = 1.0f / z;
}

// ============================================================================
// k_av: AO(128q x 64d) = P @ V, P=exp(Sc-m[k])*rZ[k], V=Q (ref bug).  grid (8, 64)
// ============================================================================
__global__ __launch_bounds__(256) void k_av()
{
    __shared__ __nv_bfloat16 Ah[128 * SA], Al[128 * SA], Bh2[64 * SA], Bl2[64 * SA];
    __shared__ float smm[Ss], smz[Ss];
    const int t = threadIdx.x, lane = t & 31, wid = t >> 5;
    const int wm = (wid >> 2) * 64, wn = (wid & 3) * 16;   // warp tile 64 x 16
    const int q0 = blockIdx.x << 7, bh = blockIdx.y;

#pragma unroll
    for (int j = 0; j < 4; j++) {
        int idx = j * 256 + t;
        smm[idx] = g_m [bh * Ss + idx];
        smz[idx] = g_rZ[bh * Ss + idx];
    }

    float acc[4][2][4];
#pragma unroll
    for (int i = 0; i < 4; i++)
#pragma unroll
        for (int j = 0; j < 2; j++)
#pragma unroll
            for (int v = 0; v < 4; v++) acc[i][j][v] = 0.f;
    __syncthreads();

    for (int c0 = 0; c0 < Ss; c0 += 32) {
#pragma unroll
        for (int p = 0; p < 4; p++) {
            int idx = p * 256 + t, row = idx >> 3, k4 = (idx & 7) << 2;
            float4 s = *(const float4*)(g_Sc + ((size_t)bh << 20) + (size_t)(q0 + row) * Ss + c0 + k4);
            float4 pv = make_float4(
                __expf(s.x - smm[c0 + k4])     * smz[c0 + k4],
                __expf(s.y - smm[c0 + k4 + 1]) * smz[c0 + k4 + 1],
                __expf(s.z - smm[c0 + k4 + 2]) * smz[c0 + k4 + 2],
                __expf(s.w - smm[c0 + k4 + 3]) * smz[c0 + k4 + 3]);
            splitst(&Ah[row * SA + k4], &Al[row * SA + k4], pv);
        }
#pragma unroll
        for (int p = 0; p < 2; p++) {
            int idx = p * 256 + t, row = idx >> 3, k4 = (idx & 7) << 2;
            splitst(&Bh2[row * SA + k4], &Bl2[row * SA + k4],
                    *(const float4*)(g_VT + ((size_t)bh * Dd + row) * Ss + c0 + k4));
        }
        __syncthreads();
        mma_block<2>(Ah, Al, Bh2, Bl2, wm, wn, lane, acc);
        __syncthreads();
    }

    const int b = bh >> 4, h = bh & 15;
    const int gr = lane >> 2, tc = (lane & 3) * 2;
#pragma unroll
    for (int mt = 0; mt < 4; mt++)
#pragma unroll
        for (int nt = 0; nt < 2; nt++) {
            int q = q0 + wm + mt * 16 + gr, d = wn + nt * 8 + tc;
            *(float2*)(g_AO + ((size_t)b * Ss + q) * Ee + h * Dd + d) =
                make_float2(acc[mt][nt][0], acc[mt][nt][1]);
            *(float2*)(g_AO + ((size_t)b * Ss + q + 8) * Ee + h * Dd + d) =
                make_float2(acc[mt][nt][2], acc[mt][nt][3]);
        }
}

// ============================================================================
// k_oproj: out(128m x 128n) = AO @ Wo + bo.  grid (32, 8)
// ============================================================================
__global__ __launch_bounds__(256) void k_oproj(
    const float* __restrict__ bo, float* __restrict__ out)
{
    __shared__ __nv_bfloat16 Ah[128 * SA], Al[128 * SA], Bh2[128 * SA], Bl2[128 * SA];
    const int t = threadIdx.x, lane = t & 31, wid = t >> 5;
    const int wm = (wid >> 2) * 64, wn = (wid & 3) * 32;
    const int m0 = blockIdx.x << 7, n0 = blockIdx.y << 7;

    float acc[4][4][4];
#pragma unroll
    for (int i = 0; i < 4; i++)
#pragma unroll
        for (int j = 0; j < 4; j++)
#pragma unroll
            for (int v = 0; v < 4; v++) acc[i][j][v] = 0.f;

    for (int e0 = 0; e0 < Ee; e0 += 32) {
#pragma unroll
        for (int p = 0; p < 4; p++) {
            int idx = p * 256 + t, row = idx >> 3, k4 = (idx & 7) << 2;
            splitst(&Ah[row * SA + k4], &Al[row * SA + k4],
                    *(const float4*)(g_AO + (size_t)(m0 + row) * Ee + e0 + k4));
            splitst(&Bh2[row * SA + k4], &Bl2[row * SA + k4],
                    *(const float4*)(g_WoT + (size_t)(n0 + row) * Ee + e0 + k4));
        }
        __syncthreads();
        mma_block<4>(Ah, Al, Bh2, Bl2, wm, wn, lane, acc);
        __syncthreads();
    }

    const int gr = lane >> 2, tc = (lane & 3) * 2;
#pragma unroll
    for (int mt = 0; mt < 4; mt++)
#pragma unroll
        for (int nt = 0; nt < 4; nt++) {
            int m = m0 + wm + mt * 16 + gr, n = n0 + wn + nt * 8 + tc;
            float bx = bo[n], by = bo[n + 1];
            *(float2*)(out + (size_t)m * Ee + n) =
                make_float2(acc[mt][nt][0] + bx, acc[mt][nt][1] + by);
            *(float2*)(out + (size_t)(m + 8) * Ee + n) =
                make_float2(acc[mt][nt][2] + bx, acc[mt][nt][3] + by);
        }
}

// ============================================================================
extern "C" void kernel_launch(void* const* d_in, const int* in_sizes, int n_in,
                              void* d_out, int out_size)
{
    const float* x  = (const float*)d_in[0];
    const float* Wq = (const float*)d_in[1];
    const float* bq = (const float*)d_in[2];
    const float* Wk = (const float*)d_in[3];
    const float* bk = (const float*)d_in[4];
    // d_in[5], d_in[6] (W_v, b_v) intentionally unused: reference bug v = q
    const float* Wo = (const float*)d_in[7];
    const float* bo = (const float*)d_in[8];
    float* out = (float*)d_out;

    float *WqT, *WkT, *WoT, *Qp, *VTp;
    cudaGetSymbolAddress((void**)&WqT, g_WqT);
    cudaGetSymbolAddress((void**)&WkT, g_WkT);
    cudaGetSymbolAddress((void**)&WoT, g_WoT);
    cudaGetSymbolAddress((void**)&Qp,  g_Q);
    cudaGetSymbolAddress((void**)&VTp, g_VT);

    dim3 tb8(32, 8);
    k_tr<<<dim3(32, 2, 16), tb8>>>(Wq, WqT, Ee, Dd);
    k_tr<<<dim3(32, 2, 16), tb8>>>(Wk, WkT, Ee, Dd);
    k_tr<<<dim3(32, 32, 1), tb8>>>(Wo, WoT, Ee, Ee);

    k_proj    <<<dim3(Mm / 128, Hh), 256>>>(x, bq, bk);
    k_tr      <<<dim3(32, 2, BH), tb8>>>(Qp, VTp, Ss, Dd);   // V^T (= Q^T)
    k_scores  <<<dim3(Ss / 128, Ss / 128, BH), 256>>>();
    k_colstats<<<dim3(Ss / 256, BH), 256>>>();
    k_av      <<<dim3(Ss / 128, BH), 256>>>();
    k_oproj   <<<dim3(Mm / 128, Ee / 128), 256>>>(bo, out);
}

// round 5
// speedup vs baseline: 1.4060x; 1.0743x over previous
#include <cuda_runtime.h>
#include <cuda_bf16.h>
#include <cstdint>

#define Ss 1024
#define Ee 1024
#define Hh 16
#define Dd 64
#define BH 64
#define Mm 4096
#define SB 72            // smem row stride in bf16 (BK=64 + 8 pad)
#define STG 73728u       // one pipeline stage: 4 arrays x 18432 B

typedef __nv_bfloat16 bf16;

// ----------------- scratch (static device globals) -----------------
__device__ bf16 g_xh[Mm * Ee],      g_xl[Mm * Ee];
__device__ bf16 g_Wqkh[Hh * 128 * Ee], g_Wqkl[Hh * 128 * Ee];  // [h][0:64 Wq d | 64:128 Wk d][e]
__device__ bf16 g_Woh[Ee * Ee],     g_Wol[Ee * Ee];            // [n][e]
__device__ bf16 g_Qh[BH * Ss * Dd], g_Ql[BH * Ss * Dd];
__device__ bf16 g_Kh[BH * Ss * Dd], g_Kl[BH * Ss * Dd];
__device__ bf16 g_VTh[BH * Dd * Ss], g_VTl[BH * Dd * Ss];
__device__ bf16 g_AOh[Mm * Ee],     g_AOl[Mm * Ee];
__device__ float g_Sc[(size_t)BH * Ss * Ss];
__device__ float g_m[BH * Ss], g_rZ[BH * Ss];

// ----------------- helpers -----------------
__device__ __forceinline__ uint32_t smem_u32(const void* p) {
    uint32_t a;
    asm("{ .reg .u64 t; cvta.to.shared.u64 t, %1; cvt.u32.u64 %0, t; }" : "=r"(a) : "l"(p));
    return a;
}
__device__ __forceinline__ uint32_t pk2f(float a, float b) {
    bf16 x = __float2bfloat16(a), y = __float2bfloat16(b);
    return (uint32_t)*(uint16_t*)&x | ((uint32_t)*(uint16_t*)&y << 16);
}
__device__ __forceinline__ void splitst(bf16* hp, bf16* lp, float4 v) {
    bf16 hx = __float2bfloat16(v.x), hy = __float2bfloat16(v.y);
    bf16 hz = __float2bfloat16(v.z), hw = __float2bfloat16(v.w);
    *(uint32_t*)hp       = (uint32_t)*(uint16_t*)&hx | ((uint32_t)*(uint16_t*)&hy << 16);
    *(uint32_t*)(hp + 2) = (uint32_t)*(uint16_t*)&hz | ((uint32_t)*(uint16_t*)&hw << 16);
    *(uint32_t*)lp       = pk2f(v.x - __bfloat162float(hx), v.y - __bfloat162float(hy));
    *(uint32_t*)(lp + 2) = pk2f(v.z - __bfloat162float(hz), v.w - __bfloat162float(hw));
}
__device__ __forceinline__ void wr_split(bf16* oh, bf16* ol, size_t idx, float a, float b) {
    bf16 ha = __float2bfloat16(a), hb = __float2bfloat16(b);
    *(uint32_t*)(oh + idx) = (uint32_t)*(uint16_t*)&ha | ((uint32_t)*(uint16_t*)&hb << 16);
    *(uint32_t*)(ol + idx) = pk2f(a - __bfloat162float(ha), b - __bfloat162float(hb));
}
__device__ __forceinline__ void mma16816(float* c, const uint32_t a[4], uint32_t b0, uint32_t b1) {
    asm volatile("mma.sync.aligned.m16n8k16.row.col.f32.bf16.bf16.f32 "
                 "{%0,%1,%2,%3}, {%4,%5,%6,%7}, {%8,%9}, {%0,%1,%2,%3};"
                 : "+f"(c[0]), "+f"(c[1]), "+f"(c[2]), "+f"(c[3])
                 : "r"(a[0]), "r"(a[1]), "r"(a[2]), "r"(a[3]), "r"(b0), "r"(b1));
}
__device__ __forceinline__ void cpasync16(uint32_t dst, const void* src) {
    asm volatile("cp.async.cg.shared.global [%0], [%1], 16;" :: "r"(dst), "l"(src));
}
__device__ __forceinline__ void cp_commit() { asm volatile("cp.async.commit_group;" ::: "memory"); }
template<int N> __device__ __forceinline__ void cp_wait() {
    asm volatile("cp.async.wait_group %0;" :: "n"(N) : "memory");
}
// copy ROWS x 64 bf16 (rows of 128B) global -> smem stage
template<int ROWS>
__device__ __forceinline__ void cp_one(uint32_t sdst, const bf16* g, size_t ld, int t) {
#pragma unroll
    for (int i = 0; i < ROWS / 32; i++) {
        int c = i * 256 + t, row = c >> 3, cid = c & 7;
        cpasync16(sdst + row * (SB * 2) + cid * 16, g + (size_t)row * ld + cid * 8);
    }
}
// 3-term split-bf16 over one staged k-chunk of 64
template<int NT>
__device__ __forceinline__ void mma_block(const bf16* Ah, const bf16* Al,
    const bf16* Bh, const bf16* Bl, int wm, int wn, int lane, float (*acc)[NT][4])
{
    const int gr = lane >> 2, tc = (lane & 3) * 2;
#pragma unroll
    for (int ks = 0; ks < 64; ks += 16) {
        uint32_t ah[4][4], al[4][4];
#pragma unroll
        for (int mt = 0; mt < 4; mt++) {
            const bf16* pa = Ah + (wm + mt * 16 + gr) * SB + ks + tc;
            const bf16* pl = Al + (wm + mt * 16 + gr) * SB + ks + tc;
            ah[mt][0] = *(const uint32_t*)pa;
            ah[mt][1] = *(const uint32_t*)(pa + 8 * SB);
            ah[mt][2] = *(const uint32_t*)(pa + 8);
            ah[mt][3] = *(const uint32_t*)(pa + 8 * SB + 8);
            al[mt][0] = *(const uint32_t*)pl;
            al[mt][1] = *(const uint32_t*)(pl + 8 * SB);
            al[mt][2] = *(const uint32_t*)(pl + 8);
            al[mt][3] = *(const uint32_t*)(pl + 8 * SB + 8);
        }
#pragma unroll
        for (int nt = 0; nt < NT; nt++) {
            const bf16* pb = Bh + (wn + nt * 8 + gr) * SB + ks + tc;
            const bf16* pq = Bl + (wn + nt * 8 + gr) * SB + ks + tc;
            uint32_t bh0 = *(const uint32_t*)pb, bh1 = *(const uint32_t*)(pb + 8);
            uint32_t bl0 = *(const uint32_t*)pq, bl1 = *(const uint32_t*)(pq + 8);
#pragma unroll
            for (int mt = 0; mt < 4; mt++) {
                mma16816(acc[mt][nt], ah[mt], bh0, bh1);
                mma16816(acc[mt][nt], ah[mt], bl0, bl1);
                mma16816(acc[mt][nt], al[mt], bh0, bh1);
            }
        }
    }
}

// ----------------- conversion / transpose kernels -----------------
__global__ void k_cvtx(const float* __restrict__ x) {
    int idx = blockIdx.x * 256 + threadIdx.x;           // one float4 per thread
    float4 v = ((const float4*)x)[idx];
    splitst(g_xh + idx * 4, g_xl + idx * 4, v);
}
// f32 [z][R][C] -> bf16 hi/lo [z][row_off + c][R]
__global__ void k_trwf(const float* __restrict__ in, bf16* __restrict__ oh, bf16* __restrict__ ol,
                       int R, int C, size_t islab, size_t oslab, int row_off)
{
    __shared__ float tile[32][33];
    const float* I = in + (size_t)blockIdx.z * islab;
    int r0 = blockIdx.x << 5, c0 = blockIdx.y << 5;
    int tx = threadIdx.x, ty = threadIdx.y;
#pragma unroll
    for (int i = ty; i < 32; i += 8)
        tile[i][tx] = I[(size_t)(r0 + i) * C + c0 + tx];
    __syncthreads();
#pragma unroll
    for (int i = ty; i < 32; i += 8) {
        float v = tile[tx][i];
        bf16 h = __float2bfloat16(v);
        size_t o = (size_t)blockIdx.z * oslab + (size_t)(row_off + c0 + i) * R + r0 + tx;
        oh[o] = h;
        ol[o] = __float2bfloat16(v - __bfloat162float(h));
    }
}
// bf16 Q [bh][s][d] -> VT [bh][d][s] (both hi and lo)
__global__ void k_trqb()
{
    __shared__ bf16 th[32][33], tl[32][33];
    int bh = blockIdx.z, s0 = blockIdx.x << 5, d0 = blockIdx.y << 5;
    int tx = threadIdx.x, ty = threadIdx.y;
    const bf16* Ih = g_Qh + (size_t)bh * Ss * Dd;
    const bf16* Il = g_Ql + (size_t)bh * Ss * Dd;
#pragma unroll
    for (int i = ty; i < 32; i += 8) {
        th[i][tx] = Ih[(size_t)(s0 + i) * Dd + d0 + tx];
        tl[i][tx] = Il[(size_t)(s0 + i) * Dd + d0 + tx];
    }
    __syncthreads();
#pragma unroll
    for (int i = ty; i < 32; i += 8) {
        size_t o = (size_t)bh * Dd * Ss + (size_t)(d0 + i) * Ss + s0 + tx;
        g_VTh[o] = th[tx][i];
        g_VTl[o] = tl[tx][i];
    }
}

// ============================================================================
// k_proj: [Q|K](128m x 128n) = x @ Wqk^T + bias -> bf16 hi/lo Q,K.  grid (32,16)
// ============================================================================
__global__ __launch_bounds__(256, 1) void k_proj(const float* __restrict__ bq,
                                                 const float* __restrict__ bk)
{
    extern __shared__ char sm[];
    const int t = threadIdx.x, lane = t & 31, wid = t >> 5;
    const int wm = (wid >> 2) * 64, wn = (wid & 3) * 32;
    const int m0 = blockIdx.x << 7, h = blockIdx.y;
    uint32_t sb = smem_u32(sm);
    const bf16* Ahg = g_xh + (size_t)m0 * Ee;
    const bf16* Alg = g_xl + (size_t)m0 * Ee;
    const bf16* Bhg = g_Wqkh + (size_t)h * 128 * Ee;
    const bf16* Blg = g_Wqkl + (size_t)h * 128 * Ee;

    float acc[4][4][4];
#pragma unroll
    for (int i = 0; i < 4; i++)
#pragma unroll
        for (int j = 0; j < 4; j++)
#pragma unroll
            for (int v = 0; v < 4; v++) acc[i][j][v] = 0.f;

    // prologue: stage 0
    cp_one<128>(sb + 0,     Ahg, Ee, t);
    cp_one<128>(sb + 18432, Alg, Ee, t);
    cp_one<128>(sb + 36864, Bhg, Ee, t);
    cp_one<128>(sb + 55296, Blg, Ee, t);
    cp_commit();

    for (int c = 0; c < 16; c++) {
        int st = c & 1;
        if (c < 15) {
            int k0 = (c + 1) * 64;
            uint32_t nb = sb + (st ^ 1) * STG;
            cp_one<128>(nb + 0,     Ahg + k0, Ee, t);
            cp_one<128>(nb + 18432, Alg + k0, Ee, t);
            cp_one<128>(nb + 36864, Bhg + k0, Ee, t);
            cp_one<128>(nb + 55296, Blg + k0, Ee, t);
            cp_commit();
            cp_wait<1>();
        } else cp_wait<0>();
        __syncthreads();
        const char* p = sm + st * STG;
        mma_block<4>((const bf16*)p, (const bf16*)(p + 18432),
                     (const bf16*)(p + 36864), (const bf16*)(p + 55296), wm, wn, lane, acc);
        __syncthreads();
    }

    const int b = m0 >> 10, hb = b * Hh + h;
    const bool isQ = (wn < 64);
    bf16* dh = isQ ? g_Qh : g_Kh;
    bf16* dl = isQ ? g_Ql : g_Kl;
    const float* bias = (isQ ? bq : bk) + h * Dd;
    const int gr = lane >> 2, tc = (lane & 3) * 2;
#pragma unroll
    for (int mt = 0; mt < 4; mt++)
#pragma unroll
        for (int nt = 0; nt < 4; nt++) {
            int d = (wn + nt * 8 + tc) - (isQ ? 0 : 64);
            float bx = bias[d], by = bias[d + 1];
            int s = (m0 & 1023) + wm + mt * 16 + gr;
            wr_split(dh, dl, ((size_t)hb * Ss + s) * Dd + d,
                     acc[mt][nt][0] + bx, acc[mt][nt][1] + by);
            wr_split(dh, dl, ((size_t)hb * Ss + s + 8) * Dd + d,
                     acc[mt][nt][2] + bx, acc[mt][nt][3] + by);
        }
}

// ============================================================================
// k_scores: Sc(128q x 128k') = Q @ K^T / 32.  single K-chunk (D=64).  grid (8,8,64)
// ============================================================================
__global__ __launch_bounds__(256, 1) void k_scores()
{
    extern __shared__ char sm[];
    const int t = threadIdx.x, lane = t & 31, wid = t >> 5;
    const int wm = (wid >> 2) * 64, wn = (wid & 3) * 32;
    const int k0 = blockIdx.x << 7, q0 = blockIdx.y << 7, bh = blockIdx.z;
    uint32_t sb = smem_u32(sm);

    cp_one<128>(sb + 0,     g_Qh + ((size_t)bh * Ss + q0) * Dd, Dd, t);
    cp_one<128>(sb + 18432, g_Ql + ((size_t)bh * Ss + q0) * Dd, Dd, t);
    cp_one<128>(sb + 36864, g_Kh + ((size_t)bh * Ss + k0) * Dd, Dd, t);
    cp_one<128>(sb + 55296, g_Kl + ((size_t)bh * Ss + k0) * Dd, Dd, t);
    cp_commit();

    float acc[4][4][4];
#pragma unroll
    for (int i = 0; i < 4; i++)
#pragma unroll
        for (int j = 0; j < 4; j++)
#pragma unroll
            for (int v = 0; v < 4; v++) acc[i][j][v] = 0.f;

    cp_wait<0>();
    __syncthreads();
    mma_block<4>((const bf16*)sm, (const bf16*)(sm + 18432),
                 (const bf16*)(sm + 36864), (const bf16*)(sm + 55296), wm, wn, lane, acc);

    float* outp = g_Sc + ((size_t)bh << 20);
    const int gr = lane >> 2, tc = (lane & 3) * 2;
#pragma unroll
    for (int mt = 0; mt < 4; mt++)
#pragma unroll
        for (int nt = 0; nt < 4; nt++) {
            int q = q0 + wm + mt * 16 + gr, n = k0 + wn + nt * 8 + tc;
            *(float2*)(outp + (size_t)q * Ss + n) =
                make_float2(acc[mt][nt][0] * 0.03125f, acc[mt][nt][1] * 0.03125f);
            *(float2*)(outp + (size_t)(q + 8) * Ss + n) =
                make_float2(acc[mt][nt][2] * 0.03125f, acc[mt][nt][3] * 0.03125f);
        }
}

// ============================================================================
// k_colstats: per-column (over q) online max & sum-exp.  grid (4, 64)
// ============================================================================
__global__ __launch_bounds__(256) void k_colstats()
{
    const int bh = blockIdx.y;
    const int k  = (blockIdx.x << 8) + threadIdx.x;
    const float* p = g_Sc + ((size_t)bh << 20) + k;
    float mx = -1e30f, z = 0.0f;
#pragma unroll 8
    for (int q = 0; q < Ss; q++) {
        float s  = p[(size_t)q * Ss];
        float nm = fmaxf(mx, s);
        z = z * __expf(mx - nm) + __expf(s - nm);
        mx = nm;
    }
    g_m [bh * Ss + k] = mx;
    g_rZ[bh * Ss + k] = 1.0f / z;
}

// ============================================================================
// k_av: AO(128q x 64d) = P @ V, P=exp(Sc-m[k])*rZ[k], V=Q (ref bug).  grid (8,64)
// smem: A st*36864 {hi,+18432 lo}; B 73728 + st*18432 {hi,+9216 lo}; m 110592; z 114688
// ============================================================================
__global__ __launch_bounds__(256, 1) void k_av()
{
    extern __shared__ char sm[];
    const int t = threadIdx.x, lane = t & 31, wid = t >> 5;
    const int wm = (wid >> 2) * 64, wn = (wid & 3) * 16;
    const int q0 = blockIdx.x << 7, bh = blockIdx.y;
    uint32_t sb = smem_u32(sm);
    float* smm = (float*)(sm + 110592);
    float* smz = (float*)(sm + 114688);
    const float* Scb = g_Sc + ((size_t)bh << 20) + (size_t)q0 * Ss;
    const bf16* Vh = g_VTh + (size_t)bh * Dd * Ss;
    const bf16* Vl = g_VTl + (size_t)bh * Dd * Ss;

#pragma unroll
    for (int j = 0; j < 4; j++) {
        int idx = j * 256 + t;
        smm[idx] = g_m [bh * Ss + idx];
        smz[idx] = g_rZ[bh * Ss + idx];
    }
    __syncthreads();

    // A staging lambda-free helper (exp + split into stage st, chunk k0)
    // done inline below
    float acc[4][2][4];
#pragma unroll
    for (int i = 0; i < 4; i++)
#pragma unroll
        for (int j = 0; j < 2; j++)
#pragma unroll
            for (int v = 0; v < 4; v++) acc[i][j][v] = 0.f;

    // prologue: B chunk 0 + A chunk 0
    cp_one<64>(sb + 73728, Vh, Ss, t);
    cp_one<64>(sb + 82944, Vl, Ss, t);
    cp_commit();
#pragma unroll 1
    for (int p = 0; p < 8; p++) {
        int idx = p * 256 + t, row = idx >> 4, k4 = (idx & 15) << 2;
        float4 s = *(const float4*)(Scb + (size_t)row * Ss + k4);
        float4 pv = make_float4(__expf(s.x - smm[k4]) * smz[k4],
                                __expf(s.y - smm[k4 + 1]) * smz[k4 + 1],
                                __expf(s.z - smm[k4 + 2]) * smz[k4 + 2],
                                __expf(s.w - smm[k4 + 3]) * smz[k4 + 3]);
        splitst((bf16*)sm + row * SB + k4, (bf16*)(sm + 18432) + row * SB + k4, pv);
    }

    for (int c = 0; c < 16; c++) {
        int st = c & 1;
        if (c < 15) {
            int k0 = (c + 1) * 64, sn = st ^ 1;
            cp_one<64>(sb + 73728 + sn * 18432, Vh + k0, Ss, t);
            cp_one<64>(sb + 82944 + sn * 18432, Vl + k0, Ss, t);
            cp_commit();
#pragma unroll 1
            for (int p = 0; p < 8; p++) {
                int idx = p * 256 + t, row = idx >> 4, k4 = (idx & 15) << 2;
                float4 s = *(const float4*)(Scb + (size_t)row * Ss + k0 + k4);
                float4 pv = make_float4(__expf(s.x - smm[k0 + k4]) * smz[k0 + k4],
                                        __expf(s.y - smm[k0 + k4 + 1]) * smz[k0 + k4 + 1],
                                        __expf(s.z - smm[k0 + k4 + 2]) * smz[k0 + k4 + 2],
                                        __expf(s.w - smm[k0 + k4 + 3]) * smz[k0 + k4 + 3]);
                splitst((bf16*)(sm + sn * 36864) + row * SB + k4,
                        (bf16*)(sm + sn * 36864 + 18432) + row * SB + k4, pv);
            }
            cp_wait<1>();
        } else cp_wait<0>();
        __syncthreads();
        mma_block<2>((const bf16*)(sm + st * 36864), (const bf16*)(sm + st * 36864 + 18432),
                     (const bf16*)(sm + 73728 + st * 18432), (const bf16*)(sm + 82944 + st * 18432),
                     wm, wn, lane, acc);
        __syncthreads();
    }

    const int b = bh >> 4, h = bh & 15;
    const int gr = lane >> 2, tc = (lane & 3) * 2;
#pragma unroll
    for (int mt = 0; mt < 4; mt++)
#pragma unroll
        for (int nt = 0; nt < 2; nt++) {
            int q = q0 + wm + mt * 16 + gr, d = wn + nt * 8 + tc;
            wr_split(g_AOh, g_AOl, ((size_t)b * Ss + q) * Ee + h * Dd + d,
                     acc[mt][nt][0], acc[mt][nt][1]);
            wr_split(g_AOh, g_AOl, ((size_t)b * Ss + q + 8) * Ee + h * Dd + d,
                     acc[mt][nt][2], acc[mt][nt][3]);
        }
}

// ============================================================================
// k_oproj: out(128m x 128n) = AO @ Wo + bo.  grid (32, 8)
// ============================================================================
__global__ __launch_bounds__(256, 1) void k_oproj(const float* __restrict__ bo,
                                                  float* __restrict__ out)
{
    extern __shared__ char sm[];
    const int t = threadIdx.x, lane = t & 31, wid = t >> 5;
    const int wm = (wid >> 2) * 64, wn = (wid & 3) * 32;
    const int m0 = blockIdx.x << 7, n0 = blockIdx.y << 7;
    uint32_t sb = smem_u32(sm);
    const bf16* Ahg = g_AOh + (size_t)m0 * Ee;
    const bf16* Alg = g_AOl + (size_t)m0 * Ee;
    const bf16* Bhg = g_Woh + (size_t)n0 * Ee;
    const bf16* Blg = g_Wol + (size_t)n0 * Ee;

    float acc[4][4][4];
#pragma unroll
    for (int i = 0; i < 4; i++)
#pragma unroll
        for (int j = 0; j < 4; j++)
#pragma unroll
            for (int v = 0; v < 4; v++) acc[i][j][v] = 0.f;

    cp_one<128>(sb + 0,     Ahg, Ee, t);
    cp_one<128>(sb + 18432, Alg, Ee, t);
    cp_one<128>(sb + 36864, Bhg, Ee, t);
    cp_one<128>(sb + 55296, Blg, Ee, t);
    cp_commit();

    for (int c = 0; c < 16; c++) {
        int st = c & 1;
        if (c < 15) {
            int k0 = (c + 1) * 64;
            uint32_t nb = sb + (st ^ 1) * STG;
            cp_one<128>(nb + 0,     Ahg + k0, Ee, t);
            cp_one<128>(nb + 18432, Alg + k0, Ee, t);
            cp_one<128>(nb + 36864, Bhg + k0, Ee, t);
            cp_one<128>(nb + 55296, Blg + k0, Ee, t);
            cp_commit();
            cp_wait<1>();
        } else cp_wait<0>();
        __syncthreads();
        const char* p = sm + st * STG;
        mma_block<4>((const bf16*)p, (const bf16*)(p + 18432),
                     (const bf16*)(p + 36864), (const bf16*)(p + 55296), wm, wn, lane, acc);
        __syncthreads();
    }

    const int gr = lane >> 2, tc = (lane & 3) * 2;
#pragma unroll
    for (int mt = 0; mt < 4; mt++)
#pragma unroll
        for (int nt = 0; nt < 4; nt++) {
            int m = m0 + wm + mt * 16 + gr, n = n0 + wn + nt * 8 + tc;
            float bx = bo[n], by = bo[n + 1];
            *(float2*)(out + (size_t)m * Ee + n) =
                make_float2(acc[mt][nt][0] + bx, acc[mt][nt][1] + by);
            *(float2*)(out + (size_t)(m + 8) * Ee + n) =
                make_float2(acc[mt][nt][2] + bx, acc[mt][nt][3] + by);
        }
}

// ============================================================================
extern "C" void kernel_launch(void* const* d_in, const int* in_sizes, int n_in,
                              void* d_out, int out_size)
{
    const float* x  = (const float*)d_in[0];
    const float* Wq = (const float*)d_in[1];
    const float* bq = (const float*)d_in[2];
    const float* Wk = (const float*)d_in[3];
    const float* bk = (const float*)d_in[4];
    // d_in[5], d_in[6] (W_v, b_v) intentionally unused: reference bug v = q
    const float* Wo = (const float*)d_in[7];
    const float* bo = (const float*)d_in[8];
    float* out = (float*)d_out;

    cudaFuncSetAttribute(k_proj,   cudaFuncAttributeMaxDynamicSharedMemorySize, 147456);
    cudaFuncSetAttribute(k_scores, cudaFuncAttributeMaxDynamicSharedMemorySize, 73728);
    cudaFuncSetAttribute(k_av,     cudaFuncAttributeMaxDynamicSharedMemorySize, 118784);
    cudaFuncSetAttribute(k_oproj,  cudaFuncAttributeMaxDynamicSharedMemorySize, 147456);

    bf16 *Wqkh, *Wqkl, *Woh, *Wol;
    cudaGetSymbolAddress((void**)&Wqkh, g_Wqkh);
    cudaGetSymbolAddress((void**)&Wqkl, g_Wqkl);
    cudaGetSymbolAddress((void**)&Woh,  g_Woh);
    cudaGetSymbolAddress((void**)&Wol,  g_Wol);

    dim3 tb8(32, 8);
    k_cvtx<<<4096, 256>>>(x);
    k_trwf<<<dim3(32, 2, 16), tb8>>>(Wq, Wqkh, Wqkl, Ee, Dd, (size_t)Ee * Dd, 128 * Ee, 0);
    k_trwf<<<dim3(32, 2, 16), tb8>>>(Wk, Wqkh, Wqkl, Ee, Dd, (size_t)Ee * Dd, 128 * Ee, 64);
    k_trwf<<<dim3(32, 32, 1), tb8>>>(Wo, Woh, Wol, Ee, Ee, (size_t)Ee * Ee, (size_t)Ee * Ee, 0);

    k_proj    <<<dim3(Mm / 128, Hh), 256, 147456>>>(bq, bk);
    k_trqb    <<<dim3(32, 2, BH), tb8>>>();
    k_scores  <<<dim3(Ss / 128, Ss / 128, BH), 256, 73728>>>();
    k_colstats<<<dim3(Ss / 256, BH), 256>>>();
    k_av      <<<dim3(Ss / 128, BH), 256, 118784>>>();
    k_oproj   <<<dim3(Mm / 128, Ee / 128), 256, 147456>>>(bo, out);
}